// round 12
// baseline (speedup 1.0000x reference)
#include <cuda_runtime.h>
#include <cuda_fp16.h>
#include <cstdint>

// ---------------------------------------------------------------------------
// MGDCF diffusion: h_{t+1} = BETA * A_norm h_t + ALPHA * h0, K=4 steps.
// Round 11: R10 base +
//   (a) ticket-based CSR fill: count_kernel's atomicAdd return values are
//       stored as per-edge slot tickets; fill_kernel becomes atomic-free
//       (pos = rowstart[dst] + ticket).
//   (b) __launch_bounds__(256,6) on spmm_step1 (isolated occupancy test).
// ---------------------------------------------------------------------------

#define NUSERS 200000
#define NITEMS 100000
#define NN     300000              // total nodes (div by 4 -> exact tiling)
#define NE     1000000             // user-item pairs
#define DD     64                  // feature dim

static constexpr float ALPHA_C = 0.1f;
static constexpr float BETA_C  = 0.9f;
static constexpr double GAMMA_D =
    (0.9 * 0.9 * 0.9 * 0.9) + 0.1 * (1.0 + 0.9 + 0.81 + 0.729);   // = 1.0
static constexpr float INV_GAMMA = (float)(1.0 / GAMMA_D);

// ------------------------- device scratch (static) -------------------------
__device__ __half g_hh[2][(size_t)NN * DD];  // ping-pong fp16 h buffers (76.8 MB)
__device__ int    g_cnt[NN];                 // real in-degree (excl. self loop)
__device__ float  g_norm[NN];                // (deg incl. self)^-1/2
__device__ int2   g_rowinfo[NN];             // (segment start, real in-degree)
__device__ int    g_tick_u[NE];              // ticket for edge it->u (dst u)
__device__ int    g_tick_i[NE];              // ticket for edge u->it (dst it)
__device__ uint2  g_edge[2 * NE];            // (src, norm[src] bits), 16 MB
__device__ int    g_alloc;                   // global segment allocator

// ------------------------------ build kernels ------------------------------

__global__ void count_kernel(const int* __restrict__ uidx,
                             const int* __restrict__ iidx) {
    int e = blockIdx.x * blockDim.x + threadIdx.x;
    if (e >= NE) return;
    int u  = uidx[e];
    int it = iidx[e] + NUSERS;
    // atomic return value = this edge's slot within its dst row segment
    g_tick_u[e] = atomicAdd(&g_cnt[u], 1);   // for edge it -> u  (dst = u)
    g_tick_i[e] = atomicAdd(&g_cnt[it], 1);  // for edge u -> it  (dst = it)
}

__global__ void alloc_kernel() {
    int v    = blockIdx.x * blockDim.x + threadIdx.x;
    int lane = threadIdx.x & 31;
    int c = 0;
    if (v < NN) {
        c = g_cnt[v];
        g_norm[v] = rsqrtf((float)(c + 1));
    }
    int inc = c;
    #pragma unroll
    for (int o = 1; o < 32; o <<= 1) {
        int t = __shfl_up_sync(0xFFFFFFFFu, inc, o);
        if (lane >= o) inc += t;
    }
    int total = __shfl_sync(0xFFFFFFFFu, inc, 31);
    int base = 0;
    if (lane == 31) base = atomicAdd(&g_alloc, total);
    base = __shfl_sync(0xFFFFFFFFu, base, 31);
    if (v < NN) {
        int st = base + inc - c;
        g_rowinfo[v] = make_int2(st, c);
    }
}

// Atomic-free fill: slot = rowstart[dst] + ticket.
__global__ void fill_kernel(const int* __restrict__ uidx,
                            const int* __restrict__ iidx) {
    int e = blockIdx.x * blockDim.x + threadIdx.x;
    if (e >= NE) return;
    int u  = uidx[e];
    int it = iidx[e] + NUSERS;
    float nu = g_norm[u];
    float ni = g_norm[it];
    int su = g_rowinfo[u].x;                 // rowstart of dst=u
    int si = g_rowinfo[it].x;                // rowstart of dst=it
    // edge u -> it (dst = it)
    g_edge[si + g_tick_i[e]] = make_uint2((unsigned)u, __float_as_uint(nu));
    // edge it -> u (dst = u)
    g_edge[su + g_tick_u[e]] = make_uint2((unsigned)it, __float_as_uint(ni));
}

// ----------------------- 8-wide row load/store helpers ----------------------
// Mapping A (fp16 rows): lane `sub` owns columns [sub*8, sub*8+8).

__device__ __forceinline__ void loadRow8(const float* __restrict__ h,
                                         unsigned row, int sub, float v[8]) {
    const float4* p = (const float4*)(h + (size_t)row * DD) + sub * 2;
    float4 a = p[0];
    float4 b = p[1];
    v[0]=a.x; v[1]=a.y; v[2]=a.z; v[3]=a.w;
    v[4]=b.x; v[5]=b.y; v[6]=b.z; v[7]=b.w;
}
__device__ __forceinline__ void loadRow8(const __half* __restrict__ h,
                                         unsigned row, int sub, float v[8]) {
    uint4 r = ((const uint4*)(h + (size_t)row * DD))[sub];
    float2 f0 = __half22float2(*(__half2*)&r.x);
    float2 f1 = __half22float2(*(__half2*)&r.y);
    float2 f2 = __half22float2(*(__half2*)&r.z);
    float2 f3 = __half22float2(*(__half2*)&r.w);
    v[0]=f0.x; v[1]=f0.y; v[2]=f1.x; v[3]=f1.y;
    v[4]=f2.x; v[5]=f2.y; v[6]=f3.x; v[7]=f3.y;
}
__device__ __forceinline__ void storeRow8(float* __restrict__ h,
                                          unsigned row, int sub, const float v[8]) {
    float4* p = (float4*)(h + (size_t)row * DD) + sub * 2;
    p[0] = make_float4(v[0], v[1], v[2], v[3]);
    p[1] = make_float4(v[4], v[5], v[6], v[7]);
}
__device__ __forceinline__ void storeRow8(__half* __restrict__ h,
                                          unsigned row, int sub, const float v[8]) {
    __half2 h0 = __floats2half2_rn(v[0], v[1]);
    __half2 h1 = __floats2half2_rn(v[2], v[3]);
    __half2 h2 = __floats2half2_rn(v[4], v[5]);
    __half2 h3 = __floats2half2_rn(v[6], v[7]);
    uint4 r;
    r.x = *(unsigned*)&h0;  r.y = *(unsigned*)&h1;
    r.z = *(unsigned*)&h2;  r.w = *(unsigned*)&h3;
    ((uint4*)(h + (size_t)row * DD))[sub] = r;
}

// Mapping B (fp32 rows, coalesced): lane `sub` owns columns
// {4*sub..+4} and {32+4*sub..+4}; loads are p[sub], p[sub+8] (128B coalesced).
__device__ __forceinline__ void loadRowB(const float* __restrict__ h,
                                         unsigned row, int sub, float v[8]) {
    const float4* p = (const float4*)(h + (size_t)row * DD);
    float4 a = p[sub];
    float4 b = p[sub + 8];
    v[0]=a.x; v[1]=a.y; v[2]=a.z; v[3]=a.w;
    v[4]=b.x; v[5]=b.y; v[6]=b.z; v[7]=b.w;
}
__device__ __forceinline__ void storeRowB(__half* __restrict__ h,
                                          unsigned row, int sub, const float v[8]) {
    __half2 q0 = __floats2half2_rn(v[0], v[1]);
    __half2 q1 = __floats2half2_rn(v[2], v[3]);
    __half2 q2 = __floats2half2_rn(v[4], v[5]);
    __half2 q3 = __floats2half2_rn(v[6], v[7]);
    uint2 r0, r1;
    r0.x = *(unsigned*)&q0;  r0.y = *(unsigned*)&q1;   // cols 4*sub..+4
    r1.x = *(unsigned*)&q2;  r1.y = *(unsigned*)&q3;   // cols 32+4*sub..+4
    uint2* p = (uint2*)(h + (size_t)row * DD);
    p[sub]     = r0;
    p[sub + 8] = r1;
}

// --------------------------- SpMM kernel (fp16 src) -------------------------
// Four rows per warp, 8 lanes/row, mapping A. User rows (deg~5): 8 unrolled
// slots; item rows (deg~10): 16 unrolled slots; scalar tails.
template <typename DstT>
__global__ void __launch_bounds__(256, 6)
spmm_kernel(const __half* __restrict__ hsrc, DstT* __restrict__ hdst,
            const float* __restrict__ x, float fs) {
    const int lane = threadIdx.x & 31;
    const int sub  = lane & 7;
    const int team = lane >> 3;
    const int warp = blockIdx.x * (blockDim.x >> 5) + (threadIdx.x >> 5);
    const unsigned row = warp * 4 + team;   // exact tiling: never >= NN

    const int2 info = g_rowinfo[row];
    const int  st   = info.x;
    const int  len  = info.y;
    const float nv  = rsqrtf((float)(len + 1));

    float acc[8];
    #pragma unroll
    for (int k = 0; k < 8; k++) acc[k] = 0.f;

    if (row < NUSERS) {
        // ---- user rows: 8 unrolled slots ----
        const int n8 = (len < 8) ? len : 8;
        uint2 e0 = make_uint2(0u, 0u);
        if (sub < n8) e0 = g_edge[st + sub];
        #pragma unroll
        for (int j = 0; j < 8; j++) {
            unsigned sx = __shfl_sync(0xFFFFFFFFu, e0.x, j, 8);
            unsigned wb = __shfl_sync(0xFFFFFFFFu, e0.y, j, 8);
            if (j < n8) {
                float w = __uint_as_float(wb);
                float v[8];
                loadRow8(hsrc, sx, sub, v);
                #pragma unroll
                for (int k = 0; k < 8; k++) acc[k] = fmaf(w, v[k], acc[k]);
            }
        }
        for (int j = 8; j < len; j++) {               // deg > 8 tail (~7%)
            uint2 e2 = g_edge[st + j];
            float w = __uint_as_float(e2.y);
            float v[8];
            loadRow8(hsrc, e2.x, sub, v);
            #pragma unroll
            for (int k = 0; k < 8; k++) acc[k] = fmaf(w, v[k], acc[k]);
        }
    } else {
        // ---- item rows: 16 unrolled slots ----
        const int n16 = (len < 16) ? len : 16;
        uint2 e0 = make_uint2(0u, 0u);
        uint2 e1 = make_uint2(0u, 0u);
        if (sub < n16)     e0 = g_edge[st + sub];
        if (sub + 8 < n16) e1 = g_edge[st + sub + 8];
        #pragma unroll
        for (int j = 0; j < 16; j++) {
            unsigned sx = __shfl_sync(0xFFFFFFFFu, (j < 8) ? e0.x : e1.x, j & 7, 8);
            unsigned wb = __shfl_sync(0xFFFFFFFFu, (j < 8) ? e0.y : e1.y, j & 7, 8);
            if (j < n16) {
                float w = __uint_as_float(wb);
                float v[8];
                loadRow8(hsrc, sx, sub, v);
                #pragma unroll
                for (int k = 0; k < 8; k++) acc[k] = fmaf(w, v[k], acc[k]);
            }
        }
        for (int j = 16; j < len; j++) {              // deg > 16 tail (rare)
            uint2 e2 = g_edge[st + j];
            float w = __uint_as_float(e2.y);
            float v[8];
            loadRow8(hsrc, e2.x, sub, v);
            #pragma unroll
            for (int k = 0; k < 8; k++) acc[k] = fmaf(w, v[k], acc[k]);
        }
    }

    float sh[8], x0[8];
    loadRow8(hsrc, row, sub, sh);
    loadRow8(x,    row, sub, x0);

    const float cn = BETA_C * nv;
    const float cs = BETA_C * nv * nv;

    float r[8];
    #pragma unroll
    for (int k = 0; k < 8; k++)
        r[k] = fmaf(cn, acc[k], fmaf(cs, sh[k], ALPHA_C * x0[k])) * fs;

    storeRow8(hdst, row, sub, r);
}

// ------------------------ step-1 kernel (fp32 src = x) ----------------------
// R8 structure (no row-type branch, 16-slot loop, mapping B, folded anchor)
// with __launch_bounds__(256, 6) as the isolated occupancy experiment.
__global__ void __launch_bounds__(256, 6)
spmm_step1_kernel(const float* __restrict__ x, __half* __restrict__ hdst) {
    const int lane = threadIdx.x & 31;
    const int sub  = lane & 7;
    const int team = lane >> 3;
    const int warp = blockIdx.x * (blockDim.x >> 5) + (threadIdx.x >> 5);
    const unsigned row = warp * 4 + team;

    const int2 info = g_rowinfo[row];
    const int  st   = info.x;
    const int  len  = info.y;
    const float nv  = rsqrtf((float)(len + 1));

    float acc[8];
    #pragma unroll
    for (int k = 0; k < 8; k++) acc[k] = 0.f;

    const int n16 = (len < 16) ? len : 16;
    uint2 e0 = make_uint2(0u, 0u);
    uint2 e1 = make_uint2(0u, 0u);
    if (sub < n16)     e0 = g_edge[st + sub];
    if (sub + 8 < n16) e1 = g_edge[st + sub + 8];

    #pragma unroll
    for (int j = 0; j < 16; j++) {
        unsigned sx = __shfl_sync(0xFFFFFFFFu, (j < 8) ? e0.x : e1.x, j & 7, 8);
        unsigned wb = __shfl_sync(0xFFFFFFFFu, (j < 8) ? e0.y : e1.y, j & 7, 8);
        if (j < n16) {
            float w = __uint_as_float(wb);
            float v[8];
            loadRowB(x, sx, sub, v);
            #pragma unroll
            for (int k = 0; k < 8; k++) acc[k] = fmaf(w, v[k], acc[k]);
        }
    }

    for (int j = 16; j < len; j++) {
        uint2 e2 = g_edge[st + j];
        float w = __uint_as_float(e2.y);
        float v[8];
        loadRowB(x, e2.x, sub, v);
        #pragma unroll
        for (int k = 0; k < 8; k++) acc[k] = fmaf(w, v[k], acc[k]);
    }

    float sh[8];
    loadRowB(x, row, sub, sh);

    const float cn = BETA_C * nv;
    const float ca = BETA_C * nv * nv + ALPHA_C;    // folded self + anchor

    float r[8];
    #pragma unroll
    for (int k = 0; k < 8; k++)
        r[k] = fmaf(cn, acc[k], ca * sh[k]);

    storeRowB(hdst, row, sub, r);
}

// --------------------------------- launch ----------------------------------
extern "C" void kernel_launch(void* const* d_in, const int* in_sizes, int n_in,
                              void* d_out, int out_size) {
    const float* x    = (const float*)d_in[0];
    const int*   uidx = (const int*)  d_in[1];
    const int*   iidx = (const int*)  d_in[2];
    float*       out  = (float*)d_out;

    const int T = 256;

    void* p_cnt   = nullptr; cudaGetSymbolAddress(&p_cnt,   g_cnt);
    void* p_alloc = nullptr; cudaGetSymbolAddress(&p_alloc, g_alloc);
    void* p_hh    = nullptr; cudaGetSymbolAddress(&p_hh,    g_hh);
    __half* h0 = (__half*)p_hh;
    __half* h1 = h0 + (size_t)NN * DD;

    // ---- CSR build (ticket-based; fill has no atomics) ----
    cudaMemsetAsync(p_cnt,   0, sizeof(int) * NN);
    cudaMemsetAsync(p_alloc, 0, sizeof(int));
    count_kernel<<<(NE + T - 1) / T, T>>>(uidx, iidx);
    alloc_kernel<<<(NN + T - 1) / T, T>>>();
    fill_kernel <<<(NE + T - 1) / T, T>>>(uidx, iidx);

    // ---- K = 4 diffusion steps ----
    const int rows_per_blk = (T / 32) * 4;            // 32 rows / block
    const int spmm_blocks  = (NN + rows_per_blk - 1) / rows_per_blk;

    spmm_step1_kernel<<<spmm_blocks, T>>>(x, h0);
    spmm_kernel<__half><<<spmm_blocks, T>>>(h0, h1, x, 1.0f);
    spmm_kernel<__half><<<spmm_blocks, T>>>(h1, h0, x, 1.0f);
    spmm_kernel<float ><<<spmm_blocks, T>>>(h0, out, x, INV_GAMMA);
}

// round 13
// speedup vs baseline: 1.0651x; 1.0651x over previous
#include <cuda_runtime.h>
#include <cuda_fp16.h>
#include <cstdint>

// ---------------------------------------------------------------------------
// MGDCF diffusion: h_{t+1} = BETA * A_norm h_t + ALPHA * h0, K=4 steps.
// Round 12: R10 base (290.8us) + ONE change: the fp16-source SpMM steps
// accumulate the neighbor sum in fp16 (4x half2, HFMA2) to halve hot-loop
// instruction count. Anchor/self/epilogue remain fp32; step 1 fully fp32.
// ---------------------------------------------------------------------------

#define NUSERS 200000
#define NITEMS 100000
#define NN     300000              // total nodes (div by 4 -> exact tiling)
#define NE     1000000             // user-item pairs
#define DD     64                  // feature dim

static constexpr float ALPHA_C = 0.1f;
static constexpr float BETA_C  = 0.9f;
static constexpr double GAMMA_D =
    (0.9 * 0.9 * 0.9 * 0.9) + 0.1 * (1.0 + 0.9 + 0.81 + 0.729);   // = 1.0
static constexpr float INV_GAMMA = (float)(1.0 / GAMMA_D);

// ------------------------- device scratch (static) -------------------------
__device__ __half g_hh[2][(size_t)NN * DD];  // ping-pong fp16 h buffers (76.8 MB)
__device__ int    g_cnt[NN];                 // real in-degree (excl. self loop)
__device__ float  g_norm[NN];                // (deg incl. self)^-1/2
__device__ int2   g_rowinfo[NN];             // (segment start, real in-degree)
__device__ int    g_cursor[NN];              // fill cursors
__device__ uint2  g_edge[2 * NE];            // (src, norm[src] bits), 16 MB
__device__ int    g_alloc;                   // global segment allocator

// ------------------------------ build kernels ------------------------------

__global__ void count_kernel(const int* __restrict__ uidx,
                             const int* __restrict__ iidx) {
    int e = blockIdx.x * blockDim.x + threadIdx.x;
    if (e >= NE) return;
    int u  = uidx[e];
    int it = iidx[e] + NUSERS;
    atomicAdd(&g_cnt[u], 1);
    atomicAdd(&g_cnt[it], 1);
}

__global__ void alloc_kernel() {
    int v    = blockIdx.x * blockDim.x + threadIdx.x;
    int lane = threadIdx.x & 31;
    int c = 0;
    if (v < NN) {
        c = g_cnt[v];
        g_norm[v] = rsqrtf((float)(c + 1));
    }
    int inc = c;
    #pragma unroll
    for (int o = 1; o < 32; o <<= 1) {
        int t = __shfl_up_sync(0xFFFFFFFFu, inc, o);
        if (lane >= o) inc += t;
    }
    int total = __shfl_sync(0xFFFFFFFFu, inc, 31);
    int base = 0;
    if (lane == 31) base = atomicAdd(&g_alloc, total);
    base = __shfl_sync(0xFFFFFFFFu, base, 31);
    if (v < NN) {
        int st = base + inc - c;
        g_rowinfo[v] = make_int2(st, c);
        g_cursor[v]  = st;
    }
}

__global__ void fill_kernel(const int* __restrict__ uidx,
                            const int* __restrict__ iidx) {
    int e = blockIdx.x * blockDim.x + threadIdx.x;
    if (e >= NE) return;
    int u  = uidx[e];
    int it = iidx[e] + NUSERS;
    float nu = g_norm[u];
    float ni = g_norm[it];
    int p0 = atomicAdd(&g_cursor[it], 1);
    g_edge[p0] = make_uint2((unsigned)u, __float_as_uint(nu));
    int p1 = atomicAdd(&g_cursor[u], 1);
    g_edge[p1] = make_uint2((unsigned)it, __float_as_uint(ni));
}

// ----------------------- 8-wide row load/store helpers ----------------------
// Mapping A (fp16 rows): lane `sub` owns columns [sub*8, sub*8+8).

__device__ __forceinline__ void loadRow8(const float* __restrict__ h,
                                         unsigned row, int sub, float v[8]) {
    const float4* p = (const float4*)(h + (size_t)row * DD) + sub * 2;
    float4 a = p[0];
    float4 b = p[1];
    v[0]=a.x; v[1]=a.y; v[2]=a.z; v[3]=a.w;
    v[4]=b.x; v[5]=b.y; v[6]=b.z; v[7]=b.w;
}
__device__ __forceinline__ void loadRow8(const __half* __restrict__ h,
                                         unsigned row, int sub, float v[8]) {
    uint4 r = ((const uint4*)(h + (size_t)row * DD))[sub];
    float2 f0 = __half22float2(*(__half2*)&r.x);
    float2 f1 = __half22float2(*(__half2*)&r.y);
    float2 f2 = __half22float2(*(__half2*)&r.z);
    float2 f3 = __half22float2(*(__half2*)&r.w);
    v[0]=f0.x; v[1]=f0.y; v[2]=f1.x; v[3]=f1.y;
    v[4]=f2.x; v[5]=f2.y; v[6]=f3.x; v[7]=f3.y;
}
__device__ __forceinline__ void storeRow8(float* __restrict__ h,
                                          unsigned row, int sub, const float v[8]) {
    float4* p = (float4*)(h + (size_t)row * DD) + sub * 2;
    p[0] = make_float4(v[0], v[1], v[2], v[3]);
    p[1] = make_float4(v[4], v[5], v[6], v[7]);
}
__device__ __forceinline__ void storeRow8(__half* __restrict__ h,
                                          unsigned row, int sub, const float v[8]) {
    __half2 h0 = __floats2half2_rn(v[0], v[1]);
    __half2 h1 = __floats2half2_rn(v[2], v[3]);
    __half2 h2 = __floats2half2_rn(v[4], v[5]);
    __half2 h3 = __floats2half2_rn(v[6], v[7]);
    uint4 r;
    r.x = *(unsigned*)&h0;  r.y = *(unsigned*)&h1;
    r.z = *(unsigned*)&h2;  r.w = *(unsigned*)&h3;
    ((uint4*)(h + (size_t)row * DD))[sub] = r;
}

// Mapping B (fp32 rows, coalesced): lane `sub` owns columns
// {4*sub..+4} and {32+4*sub..+4}; loads are p[sub], p[sub+8] (128B coalesced).
__device__ __forceinline__ void loadRowB(const float* __restrict__ h,
                                         unsigned row, int sub, float v[8]) {
    const float4* p = (const float4*)(h + (size_t)row * DD);
    float4 a = p[sub];
    float4 b = p[sub + 8];
    v[0]=a.x; v[1]=a.y; v[2]=a.z; v[3]=a.w;
    v[4]=b.x; v[5]=b.y; v[6]=b.z; v[7]=b.w;
}
__device__ __forceinline__ void storeRowB(__half* __restrict__ h,
                                          unsigned row, int sub, const float v[8]) {
    __half2 q0 = __floats2half2_rn(v[0], v[1]);
    __half2 q1 = __floats2half2_rn(v[2], v[3]);
    __half2 q2 = __floats2half2_rn(v[4], v[5]);
    __half2 q3 = __floats2half2_rn(v[6], v[7]);
    uint2 r0, r1;
    r0.x = *(unsigned*)&q0;  r0.y = *(unsigned*)&q1;   // cols 4*sub..+4
    r1.x = *(unsigned*)&q2;  r1.y = *(unsigned*)&q3;   // cols 32+4*sub..+4
    uint2* p = (uint2*)(h + (size_t)row * DD);
    p[sub]     = r0;
    p[sub + 8] = r1;
}

// --------------------------- SpMM kernel (fp16 src) -------------------------
// Four rows per warp, 8 lanes/row, mapping A. Neighbor sum accumulated in
// fp16 (4x half2, HFMA2); self/anchor/epilogue in fp32. User rows: 8 slots,
// item rows: 16 slots, scalar tails.
template <typename DstT>
__global__ void __launch_bounds__(256, 6)
spmm_kernel(const __half* __restrict__ hsrc, DstT* __restrict__ hdst,
            const float* __restrict__ x, float fs) {
    const int lane = threadIdx.x & 31;
    const int sub  = lane & 7;
    const int team = lane >> 3;
    const int warp = blockIdx.x * (blockDim.x >> 5) + (threadIdx.x >> 5);
    const unsigned row = warp * 4 + team;   // exact tiling: never >= NN

    const int2 info = g_rowinfo[row];
    const int  st   = info.x;
    const int  len  = info.y;
    const float nv  = rsqrtf((float)(len + 1));

    __half2 hacc0 = __float2half2_rn(0.f);
    __half2 hacc1 = hacc0, hacc2 = hacc0, hacc3 = hacc0;
    const __half2* hrow;

    if (row < NUSERS) {
        // ---- user rows: 8 unrolled slots ----
        const int n8 = (len < 8) ? len : 8;
        uint2 e0 = make_uint2(0u, 0u);
        if (sub < n8) e0 = g_edge[st + sub];
        #pragma unroll
        for (int j = 0; j < 8; j++) {
            unsigned sx = __shfl_sync(0xFFFFFFFFu, e0.x, j, 8);
            unsigned wb = __shfl_sync(0xFFFFFFFFu, e0.y, j, 8);
            if (j < n8) {
                __half2 wh = __float2half2_rn(__uint_as_float(wb));
                uint4 r = ((const uint4*)(hsrc + (size_t)sx * DD))[sub];
                hacc0 = __hfma2(*(__half2*)&r.x, wh, hacc0);
                hacc1 = __hfma2(*(__half2*)&r.y, wh, hacc1);
                hacc2 = __hfma2(*(__half2*)&r.z, wh, hacc2);
                hacc3 = __hfma2(*(__half2*)&r.w, wh, hacc3);
            }
        }
        for (int j = 8; j < len; j++) {               // deg > 8 tail (~7%)
            uint2 e2 = g_edge[st + j];
            __half2 wh = __float2half2_rn(__uint_as_float(e2.y));
            uint4 r = ((const uint4*)(hsrc + (size_t)e2.x * DD))[sub];
            hacc0 = __hfma2(*(__half2*)&r.x, wh, hacc0);
            hacc1 = __hfma2(*(__half2*)&r.y, wh, hacc1);
            hacc2 = __hfma2(*(__half2*)&r.z, wh, hacc2);
            hacc3 = __hfma2(*(__half2*)&r.w, wh, hacc3);
        }
    } else {
        // ---- item rows: 16 unrolled slots ----
        const int n16 = (len < 16) ? len : 16;
        uint2 e0 = make_uint2(0u, 0u);
        uint2 e1 = make_uint2(0u, 0u);
        if (sub < n16)     e0 = g_edge[st + sub];
        if (sub + 8 < n16) e1 = g_edge[st + sub + 8];
        #pragma unroll
        for (int j = 0; j < 16; j++) {
            unsigned sx = __shfl_sync(0xFFFFFFFFu, (j < 8) ? e0.x : e1.x, j & 7, 8);
            unsigned wb = __shfl_sync(0xFFFFFFFFu, (j < 8) ? e0.y : e1.y, j & 7, 8);
            if (j < n16) {
                __half2 wh = __float2half2_rn(__uint_as_float(wb));
                uint4 r = ((const uint4*)(hsrc + (size_t)sx * DD))[sub];
                hacc0 = __hfma2(*(__half2*)&r.x, wh, hacc0);
                hacc1 = __hfma2(*(__half2*)&r.y, wh, hacc1);
                hacc2 = __hfma2(*(__half2*)&r.z, wh, hacc2);
                hacc3 = __hfma2(*(__half2*)&r.w, wh, hacc3);
            }
        }
        for (int j = 16; j < len; j++) {              // deg > 16 tail (rare)
            uint2 e2 = g_edge[st + j];
            __half2 wh = __float2half2_rn(__uint_as_float(e2.y));
            uint4 r = ((const uint4*)(hsrc + (size_t)e2.x * DD))[sub];
            hacc0 = __hfma2(*(__half2*)&r.x, wh, hacc0);
            hacc1 = __hfma2(*(__half2*)&r.y, wh, hacc1);
            hacc2 = __hfma2(*(__half2*)&r.z, wh, hacc2);
            hacc3 = __hfma2(*(__half2*)&r.w, wh, hacc3);
        }
    }

    // convert fp16 accumulators to fp32 once
    float acc[8];
    {
        float2 a0 = __half22float2(hacc0);
        float2 a1 = __half22float2(hacc1);
        float2 a2 = __half22float2(hacc2);
        float2 a3 = __half22float2(hacc3);
        acc[0]=a0.x; acc[1]=a0.y; acc[2]=a1.x; acc[3]=a1.y;
        acc[4]=a2.x; acc[5]=a2.y; acc[6]=a3.x; acc[7]=a3.y;
    }

    float sh[8], x0[8];
    loadRow8(hsrc, row, sub, sh);
    loadRow8(x,    row, sub, x0);

    const float cn = BETA_C * nv;
    const float cs = BETA_C * nv * nv;

    float r[8];
    #pragma unroll
    for (int k = 0; k < 8; k++)
        r[k] = fmaf(cn, acc[k], fmaf(cs, sh[k], ALPHA_C * x0[k])) * fs;

    storeRow8(hdst, row, sub, r);
}

// ------------------------ step-1 kernel (fp32 src = x) ----------------------
// R10 version exactly: no row-type branch, 16-slot loop, mapping B coalesced
// gathers, folded self+anchor, plain launch bounds, full fp32 accumulation.
__global__ void __launch_bounds__(256)
spmm_step1_kernel(const float* __restrict__ x, __half* __restrict__ hdst) {
    const int lane = threadIdx.x & 31;
    const int sub  = lane & 7;
    const int team = lane >> 3;
    const int warp = blockIdx.x * (blockDim.x >> 5) + (threadIdx.x >> 5);
    const unsigned row = warp * 4 + team;

    const int2 info = g_rowinfo[row];
    const int  st   = info.x;
    const int  len  = info.y;
    const float nv  = rsqrtf((float)(len + 1));

    float acc[8];
    #pragma unroll
    for (int k = 0; k < 8; k++) acc[k] = 0.f;

    const int n16 = (len < 16) ? len : 16;
    uint2 e0 = make_uint2(0u, 0u);
    uint2 e1 = make_uint2(0u, 0u);
    if (sub < n16)     e0 = g_edge[st + sub];
    if (sub + 8 < n16) e1 = g_edge[st + sub + 8];

    #pragma unroll
    for (int j = 0; j < 16; j++) {
        unsigned sx = __shfl_sync(0xFFFFFFFFu, (j < 8) ? e0.x : e1.x, j & 7, 8);
        unsigned wb = __shfl_sync(0xFFFFFFFFu, (j < 8) ? e0.y : e1.y, j & 7, 8);
        if (j < n16) {
            float w = __uint_as_float(wb);
            float v[8];
            loadRowB(x, sx, sub, v);
            #pragma unroll
            for (int k = 0; k < 8; k++) acc[k] = fmaf(w, v[k], acc[k]);
        }
    }

    for (int j = 16; j < len; j++) {
        uint2 e2 = g_edge[st + j];
        float w = __uint_as_float(e2.y);
        float v[8];
        loadRowB(x, e2.x, sub, v);
        #pragma unroll
        for (int k = 0; k < 8; k++) acc[k] = fmaf(w, v[k], acc[k]);
    }

    float sh[8];
    loadRowB(x, row, sub, sh);

    const float cn = BETA_C * nv;
    const float ca = BETA_C * nv * nv + ALPHA_C;    // folded self + anchor

    float r[8];
    #pragma unroll
    for (int k = 0; k < 8; k++)
        r[k] = fmaf(cn, acc[k], ca * sh[k]);

    storeRowB(hdst, row, sub, r);
}

// --------------------------------- launch ----------------------------------
extern "C" void kernel_launch(void* const* d_in, const int* in_sizes, int n_in,
                              void* d_out, int out_size) {
    const float* x    = (const float*)d_in[0];
    const int*   uidx = (const int*)  d_in[1];
    const int*   iidx = (const int*)  d_in[2];
    float*       out  = (float*)d_out;

    const int T = 256;

    void* p_cnt   = nullptr; cudaGetSymbolAddress(&p_cnt,   g_cnt);
    void* p_alloc = nullptr; cudaGetSymbolAddress(&p_alloc, g_alloc);
    void* p_hh    = nullptr; cudaGetSymbolAddress(&p_hh,    g_hh);
    __half* h0 = (__half*)p_hh;
    __half* h1 = h0 + (size_t)NN * DD;

    // ---- CSR build (R10 form) ----
    cudaMemsetAsync(p_cnt,   0, sizeof(int) * NN);
    cudaMemsetAsync(p_alloc, 0, sizeof(int));
    count_kernel<<<(NE + T - 1) / T, T>>>(uidx, iidx);
    alloc_kernel<<<(NN + T - 1) / T, T>>>();
    fill_kernel <<<(NE + T - 1) / T, T>>>(uidx, iidx);

    // ---- K = 4 diffusion steps ----
    const int rows_per_blk = (T / 32) * 4;            // 32 rows / block
    const int spmm_blocks  = (NN + rows_per_blk - 1) / rows_per_blk;

    spmm_step1_kernel<<<spmm_blocks, T>>>(x, h0);
    spmm_kernel<__half><<<spmm_blocks, T>>>(h0, h1, x, 1.0f);
    spmm_kernel<__half><<<spmm_blocks, T>>>(h1, h0, x, 1.0f);
    spmm_kernel<float ><<<spmm_blocks, T>>>(h0, out, x, INV_GAMMA);
}

// round 14
// speedup vs baseline: 1.1134x; 1.0453x over previous
#include <cuda_runtime.h>
#include <cuda_fp16.h>
#include <cstdint>

// ---------------------------------------------------------------------------
// MGDCF diffusion: h_{t+1} = BETA * A_norm h_t + ALPHA * h0, K=4 steps.
// Round 13: R12 base (282.7us) +
//   (a) alloc_kernel: block-aggregated allocator (1 atomic per block),
//   (b) __ldcs streaming loads for the fp32 x anchor in fp16 steps,
//   (c) __stcs streaming stores for the final fp32 output.
// ---------------------------------------------------------------------------

#define NUSERS 200000
#define NITEMS 100000
#define NN     300000              // total nodes (div by 4 -> exact tiling)
#define NE     1000000             // user-item pairs
#define DD     64                  // feature dim

static constexpr float ALPHA_C = 0.1f;
static constexpr float BETA_C  = 0.9f;
static constexpr double GAMMA_D =
    (0.9 * 0.9 * 0.9 * 0.9) + 0.1 * (1.0 + 0.9 + 0.81 + 0.729);   // = 1.0
static constexpr float INV_GAMMA = (float)(1.0 / GAMMA_D);

// ------------------------- device scratch (static) -------------------------
__device__ __half g_hh[2][(size_t)NN * DD];  // ping-pong fp16 h buffers (76.8 MB)
__device__ int    g_cnt[NN];                 // real in-degree (excl. self loop)
__device__ float  g_norm[NN];                // (deg incl. self)^-1/2
__device__ int2   g_rowinfo[NN];             // (segment start, real in-degree)
__device__ int    g_cursor[NN];              // fill cursors
__device__ uint2  g_edge[2 * NE];            // (src, norm[src] bits), 16 MB
__device__ int    g_alloc;                   // global segment allocator

// ------------------------------ build kernels ------------------------------

__global__ void count_kernel(const int* __restrict__ uidx,
                             const int* __restrict__ iidx) {
    int e = blockIdx.x * blockDim.x + threadIdx.x;
    if (e >= NE) return;
    int u  = uidx[e];
    int it = iidx[e] + NUSERS;
    atomicAdd(&g_cnt[u], 1);
    atomicAdd(&g_cnt[it], 1);
}

// Block-aggregated segment allocation: warp scan -> smem warp totals ->
// width-8 scan -> ONE global atomic per block.
__global__ void alloc_kernel() {
    __shared__ int warp_pref[8];   // exclusive prefix of each warp's total
    __shared__ int block_base;

    int v    = blockIdx.x * blockDim.x + threadIdx.x;
    int lane = threadIdx.x & 31;
    int wid  = threadIdx.x >> 5;

    int c = 0;
    if (v < NN) {
        c = g_cnt[v];
        g_norm[v] = rsqrtf((float)(c + 1));
    }
    // inclusive warp scan
    int inc = c;
    #pragma unroll
    for (int o = 1; o < 32; o <<= 1) {
        int t = __shfl_up_sync(0xFFFFFFFFu, inc, o);
        if (lane >= o) inc += t;
    }
    if (lane == 31) warp_pref[wid] = inc;   // warp total (temporarily)
    __syncthreads();

    if (threadIdx.x < 8) {
        int t = warp_pref[threadIdx.x];
        int s = t;
        #pragma unroll
        for (int o = 1; o < 8; o <<= 1) {
            int tt = __shfl_up_sync(0xFFu, s, o, 8);
            if (threadIdx.x >= o) s += tt;
        }
        warp_pref[threadIdx.x] = s - t;     // exclusive prefix of warps
        if (threadIdx.x == 7)
            block_base = atomicAdd(&g_alloc, s);   // block total
    }
    __syncthreads();

    if (v < NN) {
        int st = block_base + warp_pref[wid] + inc - c;
        g_rowinfo[v] = make_int2(st, c);
        g_cursor[v]  = st;
    }
}

__global__ void fill_kernel(const int* __restrict__ uidx,
                            const int* __restrict__ iidx) {
    int e = blockIdx.x * blockDim.x + threadIdx.x;
    if (e >= NE) return;
    int u  = uidx[e];
    int it = iidx[e] + NUSERS;
    float nu = g_norm[u];
    float ni = g_norm[it];
    int p0 = atomicAdd(&g_cursor[it], 1);
    g_edge[p0] = make_uint2((unsigned)u, __float_as_uint(nu));
    int p1 = atomicAdd(&g_cursor[u], 1);
    g_edge[p1] = make_uint2((unsigned)it, __float_as_uint(ni));
}

// ----------------------- 8-wide row load/store helpers ----------------------
// Mapping A (fp16 rows): lane `sub` owns columns [sub*8, sub*8+8).

// fp32 anchor read, streaming (evict-first): x rows are read once per step
// and must not displace the gather-hot h working set in L2.
__device__ __forceinline__ void loadRow8F_cs(const float* __restrict__ h,
                                             unsigned row, int sub, float v[8]) {
    const float4* p = (const float4*)(h + (size_t)row * DD) + sub * 2;
    float4 a = __ldcs(p);
    float4 b = __ldcs(p + 1);
    v[0]=a.x; v[1]=a.y; v[2]=a.z; v[3]=a.w;
    v[4]=b.x; v[5]=b.y; v[6]=b.z; v[7]=b.w;
}
__device__ __forceinline__ void loadRow8(const __half* __restrict__ h,
                                         unsigned row, int sub, float v[8]) {
    uint4 r = ((const uint4*)(h + (size_t)row * DD))[sub];
    float2 f0 = __half22float2(*(__half2*)&r.x);
    float2 f1 = __half22float2(*(__half2*)&r.y);
    float2 f2 = __half22float2(*(__half2*)&r.z);
    float2 f3 = __half22float2(*(__half2*)&r.w);
    v[0]=f0.x; v[1]=f0.y; v[2]=f1.x; v[3]=f1.y;
    v[4]=f2.x; v[5]=f2.y; v[6]=f3.x; v[7]=f3.y;
}
// final fp32 output store, streaming (never re-read)
__device__ __forceinline__ void storeRow8(float* __restrict__ h,
                                          unsigned row, int sub, const float v[8]) {
    float4* p = (float4*)(h + (size_t)row * DD) + sub * 2;
    __stcs(p,     make_float4(v[0], v[1], v[2], v[3]));
    __stcs(p + 1, make_float4(v[4], v[5], v[6], v[7]));
}
__device__ __forceinline__ void storeRow8(__half* __restrict__ h,
                                          unsigned row, int sub, const float v[8]) {
    __half2 h0 = __floats2half2_rn(v[0], v[1]);
    __half2 h1 = __floats2half2_rn(v[2], v[3]);
    __half2 h2 = __floats2half2_rn(v[4], v[5]);
    __half2 h3 = __floats2half2_rn(v[6], v[7]);
    uint4 r;
    r.x = *(unsigned*)&h0;  r.y = *(unsigned*)&h1;
    r.z = *(unsigned*)&h2;  r.w = *(unsigned*)&h3;
    ((uint4*)(h + (size_t)row * DD))[sub] = r;
}

// Mapping B (fp32 rows, coalesced): lane `sub` owns columns
// {4*sub..+4} and {32+4*sub..+4}; loads are p[sub], p[sub+8] (128B coalesced).
__device__ __forceinline__ void loadRowB(const float* __restrict__ h,
                                         unsigned row, int sub, float v[8]) {
    const float4* p = (const float4*)(h + (size_t)row * DD);
    float4 a = p[sub];
    float4 b = p[sub + 8];
    v[0]=a.x; v[1]=a.y; v[2]=a.z; v[3]=a.w;
    v[4]=b.x; v[5]=b.y; v[6]=b.z; v[7]=b.w;
}
__device__ __forceinline__ void storeRowB(__half* __restrict__ h,
                                          unsigned row, int sub, const float v[8]) {
    __half2 q0 = __floats2half2_rn(v[0], v[1]);
    __half2 q1 = __floats2half2_rn(v[2], v[3]);
    __half2 q2 = __floats2half2_rn(v[4], v[5]);
    __half2 q3 = __floats2half2_rn(v[6], v[7]);
    uint2 r0, r1;
    r0.x = *(unsigned*)&q0;  r0.y = *(unsigned*)&q1;   // cols 4*sub..+4
    r1.x = *(unsigned*)&q2;  r1.y = *(unsigned*)&q3;   // cols 32+4*sub..+4
    uint2* p = (uint2*)(h + (size_t)row * DD);
    p[sub]     = r0;
    p[sub + 8] = r1;
}

// --------------------------- SpMM kernel (fp16 src) -------------------------
// Four rows per warp, 8 lanes/row, mapping A. Neighbor sum accumulated in
// fp16 (4x half2, HFMA2); self/anchor/epilogue in fp32. User rows: 8 slots,
// item rows: 16 slots, scalar tails. Anchor x read with __ldcs.
template <typename DstT>
__global__ void __launch_bounds__(256, 6)
spmm_kernel(const __half* __restrict__ hsrc, DstT* __restrict__ hdst,
            const float* __restrict__ x, float fs) {
    const int lane = threadIdx.x & 31;
    const int sub  = lane & 7;
    const int team = lane >> 3;
    const int warp = blockIdx.x * (blockDim.x >> 5) + (threadIdx.x >> 5);
    const unsigned row = warp * 4 + team;   // exact tiling: never >= NN

    const int2 info = g_rowinfo[row];
    const int  st   = info.x;
    const int  len  = info.y;
    const float nv  = rsqrtf((float)(len + 1));

    __half2 hacc0 = __float2half2_rn(0.f);
    __half2 hacc1 = hacc0, hacc2 = hacc0, hacc3 = hacc0;

    if (row < NUSERS) {
        // ---- user rows: 8 unrolled slots ----
        const int n8 = (len < 8) ? len : 8;
        uint2 e0 = make_uint2(0u, 0u);
        if (sub < n8) e0 = g_edge[st + sub];
        #pragma unroll
        for (int j = 0; j < 8; j++) {
            unsigned sx = __shfl_sync(0xFFFFFFFFu, e0.x, j, 8);
            unsigned wb = __shfl_sync(0xFFFFFFFFu, e0.y, j, 8);
            if (j < n8) {
                __half2 wh = __float2half2_rn(__uint_as_float(wb));
                uint4 r = ((const uint4*)(hsrc + (size_t)sx * DD))[sub];
                hacc0 = __hfma2(*(__half2*)&r.x, wh, hacc0);
                hacc1 = __hfma2(*(__half2*)&r.y, wh, hacc1);
                hacc2 = __hfma2(*(__half2*)&r.z, wh, hacc2);
                hacc3 = __hfma2(*(__half2*)&r.w, wh, hacc3);
            }
        }
        for (int j = 8; j < len; j++) {               // deg > 8 tail (~7%)
            uint2 e2 = g_edge[st + j];
            __half2 wh = __float2half2_rn(__uint_as_float(e2.y));
            uint4 r = ((const uint4*)(hsrc + (size_t)e2.x * DD))[sub];
            hacc0 = __hfma2(*(__half2*)&r.x, wh, hacc0);
            hacc1 = __hfma2(*(__half2*)&r.y, wh, hacc1);
            hacc2 = __hfma2(*(__half2*)&r.z, wh, hacc2);
            hacc3 = __hfma2(*(__half2*)&r.w, wh, hacc3);
        }
    } else {
        // ---- item rows: 16 unrolled slots ----
        const int n16 = (len < 16) ? len : 16;
        uint2 e0 = make_uint2(0u, 0u);
        uint2 e1 = make_uint2(0u, 0u);
        if (sub < n16)     e0 = g_edge[st + sub];
        if (sub + 8 < n16) e1 = g_edge[st + sub + 8];
        #pragma unroll
        for (int j = 0; j < 16; j++) {
            unsigned sx = __shfl_sync(0xFFFFFFFFu, (j < 8) ? e0.x : e1.x, j & 7, 8);
            unsigned wb = __shfl_sync(0xFFFFFFFFu, (j < 8) ? e0.y : e1.y, j & 7, 8);
            if (j < n16) {
                __half2 wh = __float2half2_rn(__uint_as_float(wb));
                uint4 r = ((const uint4*)(hsrc + (size_t)sx * DD))[sub];
                hacc0 = __hfma2(*(__half2*)&r.x, wh, hacc0);
                hacc1 = __hfma2(*(__half2*)&r.y, wh, hacc1);
                hacc2 = __hfma2(*(__half2*)&r.z, wh, hacc2);
                hacc3 = __hfma2(*(__half2*)&r.w, wh, hacc3);
            }
        }
        for (int j = 16; j < len; j++) {              // deg > 16 tail (rare)
            uint2 e2 = g_edge[st + j];
            __half2 wh = __float2half2_rn(__uint_as_float(e2.y));
            uint4 r = ((const uint4*)(hsrc + (size_t)e2.x * DD))[sub];
            hacc0 = __hfma2(*(__half2*)&r.x, wh, hacc0);
            hacc1 = __hfma2(*(__half2*)&r.y, wh, hacc1);
            hacc2 = __hfma2(*(__half2*)&r.z, wh, hacc2);
            hacc3 = __hfma2(*(__half2*)&r.w, wh, hacc3);
        }
    }

    // convert fp16 accumulators to fp32 once
    float acc[8];
    {
        float2 a0 = __half22float2(hacc0);
        float2 a1 = __half22float2(hacc1);
        float2 a2 = __half22float2(hacc2);
        float2 a3 = __half22float2(hacc3);
        acc[0]=a0.x; acc[1]=a0.y; acc[2]=a1.x; acc[3]=a1.y;
        acc[4]=a2.x; acc[5]=a2.y; acc[6]=a3.x; acc[7]=a3.y;
    }

    float sh[8], x0[8];
    loadRow8(hsrc, row, sub, sh);
    loadRow8F_cs(x, row, sub, x0);          // streaming anchor read

    const float cn = BETA_C * nv;
    const float cs = BETA_C * nv * nv;

    float r[8];
    #pragma unroll
    for (int k = 0; k < 8; k++)
        r[k] = fmaf(cn, acc[k], fmaf(cs, sh[k], ALPHA_C * x0[k])) * fs;

    storeRow8(hdst, row, sub, r);
}

// ------------------------ step-1 kernel (fp32 src = x) ----------------------
// R10 version: no row-type branch, 16-slot loop, mapping B coalesced gathers,
// folded self+anchor, plain launch bounds, full fp32 accumulation.
__global__ void __launch_bounds__(256)
spmm_step1_kernel(const float* __restrict__ x, __half* __restrict__ hdst) {
    const int lane = threadIdx.x & 31;
    const int sub  = lane & 7;
    const int team = lane >> 3;
    const int warp = blockIdx.x * (blockDim.x >> 5) + (threadIdx.x >> 5);
    const unsigned row = warp * 4 + team;

    const int2 info = g_rowinfo[row];
    const int  st   = info.x;
    const int  len  = info.y;
    const float nv  = rsqrtf((float)(len + 1));

    float acc[8];
    #pragma unroll
    for (int k = 0; k < 8; k++) acc[k] = 0.f;

    const int n16 = (len < 16) ? len : 16;
    uint2 e0 = make_uint2(0u, 0u);
    uint2 e1 = make_uint2(0u, 0u);
    if (sub < n16)     e0 = g_edge[st + sub];
    if (sub + 8 < n16) e1 = g_edge[st + sub + 8];

    #pragma unroll
    for (int j = 0; j < 16; j++) {
        unsigned sx = __shfl_sync(0xFFFFFFFFu, (j < 8) ? e0.x : e1.x, j & 7, 8);
        unsigned wb = __shfl_sync(0xFFFFFFFFu, (j < 8) ? e0.y : e1.y, j & 7, 8);
        if (j < n16) {
            float w = __uint_as_float(wb);
            float v[8];
            loadRowB(x, sx, sub, v);
            #pragma unroll
            for (int k = 0; k < 8; k++) acc[k] = fmaf(w, v[k], acc[k]);
        }
    }

    for (int j = 16; j < len; j++) {
        uint2 e2 = g_edge[st + j];
        float w = __uint_as_float(e2.y);
        float v[8];
        loadRowB(x, e2.x, sub, v);
        #pragma unroll
        for (int k = 0; k < 8; k++) acc[k] = fmaf(w, v[k], acc[k]);
    }

    float sh[8];
    loadRowB(x, row, sub, sh);

    const float cn = BETA_C * nv;
    const float ca = BETA_C * nv * nv + ALPHA_C;    // folded self + anchor

    float r[8];
    #pragma unroll
    for (int k = 0; k < 8; k++)
        r[k] = fmaf(cn, acc[k], ca * sh[k]);

    storeRowB(hdst, row, sub, r);
}

// --------------------------------- launch ----------------------------------
extern "C" void kernel_launch(void* const* d_in, const int* in_sizes, int n_in,
                              void* d_out, int out_size) {
    const float* x    = (const float*)d_in[0];
    const int*   uidx = (const int*)  d_in[1];
    const int*   iidx = (const int*)  d_in[2];
    float*       out  = (float*)d_out;

    const int T = 256;

    void* p_cnt   = nullptr; cudaGetSymbolAddress(&p_cnt,   g_cnt);
    void* p_alloc = nullptr; cudaGetSymbolAddress(&p_alloc, g_alloc);
    void* p_hh    = nullptr; cudaGetSymbolAddress(&p_hh,    g_hh);
    __half* h0 = (__half*)p_hh;
    __half* h1 = h0 + (size_t)NN * DD;

    // ---- CSR build ----
    cudaMemsetAsync(p_cnt,   0, sizeof(int) * NN);
    cudaMemsetAsync(p_alloc, 0, sizeof(int));
    count_kernel<<<(NE + T - 1) / T, T>>>(uidx, iidx);
    alloc_kernel<<<(NN + T - 1) / T, T>>>();
    fill_kernel <<<(NE + T - 1) / T, T>>>(uidx, iidx);

    // ---- K = 4 diffusion steps ----
    const int rows_per_blk = (T / 32) * 4;            // 32 rows / block
    const int spmm_blocks  = (NN + rows_per_blk - 1) / rows_per_blk;

    spmm_step1_kernel<<<spmm_blocks, T>>>(x, h0);
    spmm_kernel<__half><<<spmm_blocks, T>>>(h0, h1, x, 1.0f);
    spmm_kernel<__half><<<spmm_blocks, T>>>(h1, h0, x, 1.0f);
    spmm_kernel<float ><<<spmm_blocks, T>>>(h0, out, x, INV_GAMMA);
}

// round 15
// speedup vs baseline: 1.2252x; 1.1004x over previous
#include <cuda_runtime.h>
#include <cuda_fp16.h>
#include <cstdint>

// ---------------------------------------------------------------------------
// MGDCF diffusion: h_{t+1} = BETA * A_norm h_t + ALPHA * h0, K=4 steps.
// Round 14: weightless edges via feature pre-scaling. The ping-pong buffer
// stores y = norm*h (fp16). Then:
//   h_new = beta*nv*(sum_j y_j + y_self) + alpha*x ,  y_new = nv*h_new.
// Edges are 4B (src only); fp16 hot loop uses 1 shuffle + HADD2 per slot.
// Step 1 (fp32 x source) reads w = g_norm[src] from the L2-resident table.
// ---------------------------------------------------------------------------

#define NUSERS 200000
#define NITEMS 100000
#define NN     300000              // total nodes (div by 4 -> exact tiling)
#define NE     1000000             // user-item pairs
#define DD     64                  // feature dim

static constexpr float ALPHA_C = 0.1f;
static constexpr float BETA_C  = 0.9f;
static constexpr double GAMMA_D =
    (0.9 * 0.9 * 0.9 * 0.9) + 0.1 * (1.0 + 0.9 + 0.81 + 0.729);   // = 1.0
static constexpr float INV_GAMMA = (float)(1.0 / GAMMA_D);

// ------------------------- device scratch (static) -------------------------
__device__ __half   g_hh[2][(size_t)NN * DD]; // ping-pong fp16 y buffers
__device__ int      g_cnt[NN];                // real in-degree (excl. self)
__device__ float    g_norm[NN];               // (deg incl. self)^-1/2
__device__ int2     g_rowinfo[NN];            // (segment start, in-degree)
__device__ int      g_cursor[NN];             // fill cursors
__device__ unsigned g_edge[2 * NE];           // src only, 8 MB
__device__ int      g_alloc;                  // global segment allocator

// ------------------------------ build kernels ------------------------------

__global__ void count_kernel(const int* __restrict__ uidx,
                             const int* __restrict__ iidx) {
    int e = blockIdx.x * blockDim.x + threadIdx.x;
    if (e >= NE) return;
    int u  = uidx[e];
    int it = iidx[e] + NUSERS;
    atomicAdd(&g_cnt[u], 1);
    atomicAdd(&g_cnt[it], 1);
}

// Block-aggregated segment allocation: warp scan -> smem warp totals ->
// width-8 scan -> ONE global atomic per block.
__global__ void alloc_kernel() {
    __shared__ int warp_pref[8];
    __shared__ int block_base;

    int v    = blockIdx.x * blockDim.x + threadIdx.x;
    int lane = threadIdx.x & 31;
    int wid  = threadIdx.x >> 5;

    int c = 0;
    if (v < NN) {
        c = g_cnt[v];
        g_norm[v] = rsqrtf((float)(c + 1));
    }
    int inc = c;
    #pragma unroll
    for (int o = 1; o < 32; o <<= 1) {
        int t = __shfl_up_sync(0xFFFFFFFFu, inc, o);
        if (lane >= o) inc += t;
    }
    if (lane == 31) warp_pref[wid] = inc;
    __syncthreads();

    if (threadIdx.x < 8) {
        int t = warp_pref[threadIdx.x];
        int s = t;
        #pragma unroll
        for (int o = 1; o < 8; o <<= 1) {
            int tt = __shfl_up_sync(0xFFu, s, o, 8);
            if (threadIdx.x >= o) s += tt;
        }
        warp_pref[threadIdx.x] = s - t;
        if (threadIdx.x == 7)
            block_base = atomicAdd(&g_alloc, s);
    }
    __syncthreads();

    if (v < NN) {
        int st = block_base + warp_pref[wid] + inc - c;
        g_rowinfo[v] = make_int2(st, c);
        g_cursor[v]  = st;
    }
}

// fill: 4B edge payload (src only), no norm loads.
__global__ void fill_kernel(const int* __restrict__ uidx,
                            const int* __restrict__ iidx) {
    int e = blockIdx.x * blockDim.x + threadIdx.x;
    if (e >= NE) return;
    int u  = uidx[e];
    int it = iidx[e] + NUSERS;
    int p0 = atomicAdd(&g_cursor[it], 1);
    g_edge[p0] = (unsigned)u;                // edge u -> it (dst = it)
    int p1 = atomicAdd(&g_cursor[u], 1);
    g_edge[p1] = (unsigned)it;               // edge it -> u (dst = u)
}

// ----------------------- 8-wide row load/store helpers ----------------------
// Mapping A (fp16 rows): lane `sub` owns columns [sub*8, sub*8+8).

__device__ __forceinline__ void loadRow8F_cs(const float* __restrict__ h,
                                             unsigned row, int sub, float v[8]) {
    const float4* p = (const float4*)(h + (size_t)row * DD) + sub * 2;
    float4 a = __ldcs(p);
    float4 b = __ldcs(p + 1);
    v[0]=a.x; v[1]=a.y; v[2]=a.z; v[3]=a.w;
    v[4]=b.x; v[5]=b.y; v[6]=b.z; v[7]=b.w;
}
__device__ __forceinline__ void loadRow8(const __half* __restrict__ h,
                                         unsigned row, int sub, float v[8]) {
    uint4 r = ((const uint4*)(h + (size_t)row * DD))[sub];
    float2 f0 = __half22float2(*(__half2*)&r.x);
    float2 f1 = __half22float2(*(__half2*)&r.y);
    float2 f2 = __half22float2(*(__half2*)&r.z);
    float2 f3 = __half22float2(*(__half2*)&r.w);
    v[0]=f0.x; v[1]=f0.y; v[2]=f1.x; v[3]=f1.y;
    v[4]=f2.x; v[5]=f2.y; v[6]=f3.x; v[7]=f3.y;
}
__device__ __forceinline__ void storeRow8(float* __restrict__ h,
                                          unsigned row, int sub, const float v[8]) {
    float4* p = (float4*)(h + (size_t)row * DD) + sub * 2;
    __stcs(p,     make_float4(v[0], v[1], v[2], v[3]));
    __stcs(p + 1, make_float4(v[4], v[5], v[6], v[7]));
}
__device__ __forceinline__ void storeRow8(__half* __restrict__ h,
                                          unsigned row, int sub, const float v[8]) {
    __half2 h0 = __floats2half2_rn(v[0], v[1]);
    __half2 h1 = __floats2half2_rn(v[2], v[3]);
    __half2 h2 = __floats2half2_rn(v[4], v[5]);
    __half2 h3 = __floats2half2_rn(v[6], v[7]);
    uint4 r;
    r.x = *(unsigned*)&h0;  r.y = *(unsigned*)&h1;
    r.z = *(unsigned*)&h2;  r.w = *(unsigned*)&h3;
    ((uint4*)(h + (size_t)row * DD))[sub] = r;
}

// Mapping B (fp32 rows, coalesced): lane `sub` owns columns
// {4*sub..+4} and {32+4*sub..+4}; loads are p[sub], p[sub+8] (128B coalesced).
__device__ __forceinline__ void loadRowB(const float* __restrict__ h,
                                         unsigned row, int sub, float v[8]) {
    const float4* p = (const float4*)(h + (size_t)row * DD);
    float4 a = p[sub];
    float4 b = p[sub + 8];
    v[0]=a.x; v[1]=a.y; v[2]=a.z; v[3]=a.w;
    v[4]=b.x; v[5]=b.y; v[6]=b.z; v[7]=b.w;
}
__device__ __forceinline__ void storeRowB(__half* __restrict__ h,
                                          unsigned row, int sub, const float v[8]) {
    __half2 q0 = __floats2half2_rn(v[0], v[1]);
    __half2 q1 = __floats2half2_rn(v[2], v[3]);
    __half2 q2 = __floats2half2_rn(v[4], v[5]);
    __half2 q3 = __floats2half2_rn(v[6], v[7]);
    uint2 r0, r1;
    r0.x = *(unsigned*)&q0;  r0.y = *(unsigned*)&q1;
    r1.x = *(unsigned*)&q2;  r1.y = *(unsigned*)&q3;
    uint2* p = (uint2*)(h + (size_t)row * DD);
    p[sub]     = r0;
    p[sub + 8] = r1;
}

// --------------------------- SpMM kernel (fp16 y src) -----------------------
// Four rows per warp, 8 lanes/row, mapping A. Source is y = norm*h (fp16):
// hot loop is 1 shuffle + LDG.128 + 4x HADD2 per slot (no weight).
// h_new = cn*(sum_j y_j + y_self) + alpha*x ; store nv*h_new (mid steps)
// or fs*h_new (final fp32 out).
template <typename DstT, bool SCALE_OUT>
__global__ void __launch_bounds__(256, 6)
spmm_kernel(const __half* __restrict__ ysrc, DstT* __restrict__ hdst,
            const float* __restrict__ x, float fs) {
    const int lane = threadIdx.x & 31;
    const int sub  = lane & 7;
    const int team = lane >> 3;
    const int warp = blockIdx.x * (blockDim.x >> 5) + (threadIdx.x >> 5);
    const unsigned row = warp * 4 + team;   // exact tiling: never >= NN

    const int2 info = g_rowinfo[row];
    const int  st   = info.x;
    const int  len  = info.y;
    const float nv  = rsqrtf((float)(len + 1));

    __half2 hacc0 = __float2half2_rn(0.f);
    __half2 hacc1 = hacc0, hacc2 = hacc0, hacc3 = hacc0;

    if (row < NUSERS) {
        // ---- user rows: 8 unrolled slots ----
        const int n8 = (len < 8) ? len : 8;
        unsigned s0 = 0u;
        if (sub < n8) s0 = g_edge[st + sub];
        #pragma unroll
        for (int j = 0; j < 8; j++) {
            unsigned sx = __shfl_sync(0xFFFFFFFFu, s0, j, 8);
            if (j < n8) {
                uint4 r = ((const uint4*)(ysrc + (size_t)sx * DD))[sub];
                hacc0 = __hadd2(hacc0, *(__half2*)&r.x);
                hacc1 = __hadd2(hacc1, *(__half2*)&r.y);
                hacc2 = __hadd2(hacc2, *(__half2*)&r.z);
                hacc3 = __hadd2(hacc3, *(__half2*)&r.w);
            }
        }
        for (int j = 8; j < len; j++) {               // deg > 8 tail (~7%)
            unsigned sx = g_edge[st + j];
            uint4 r = ((const uint4*)(ysrc + (size_t)sx * DD))[sub];
            hacc0 = __hadd2(hacc0, *(__half2*)&r.x);
            hacc1 = __hadd2(hacc1, *(__half2*)&r.y);
            hacc2 = __hadd2(hacc2, *(__half2*)&r.z);
            hacc3 = __hadd2(hacc3, *(__half2*)&r.w);
        }
    } else {
        // ---- item rows: 16 unrolled slots ----
        const int n16 = (len < 16) ? len : 16;
        unsigned s0 = 0u, s1 = 0u;
        if (sub < n16)     s0 = g_edge[st + sub];
        if (sub + 8 < n16) s1 = g_edge[st + sub + 8];
        #pragma unroll
        for (int j = 0; j < 16; j++) {
            unsigned sx = __shfl_sync(0xFFFFFFFFu, (j < 8) ? s0 : s1, j & 7, 8);
            if (j < n16) {
                uint4 r = ((const uint4*)(ysrc + (size_t)sx * DD))[sub];
                hacc0 = __hadd2(hacc0, *(__half2*)&r.x);
                hacc1 = __hadd2(hacc1, *(__half2*)&r.y);
                hacc2 = __hadd2(hacc2, *(__half2*)&r.z);
                hacc3 = __hadd2(hacc3, *(__half2*)&r.w);
            }
        }
        for (int j = 16; j < len; j++) {              // deg > 16 tail (rare)
            unsigned sx = g_edge[st + j];
            uint4 r = ((const uint4*)(ysrc + (size_t)sx * DD))[sub];
            hacc0 = __hadd2(hacc0, *(__half2*)&r.x);
            hacc1 = __hadd2(hacc1, *(__half2*)&r.y);
            hacc2 = __hadd2(hacc2, *(__half2*)&r.z);
            hacc3 = __hadd2(hacc3, *(__half2*)&r.w);
        }
    }

    // y_self folds into the neighbor sum (same coefficient cn)
    {
        uint4 r = ((const uint4*)(ysrc + (size_t)row * DD))[sub];
        hacc0 = __hadd2(hacc0, *(__half2*)&r.x);
        hacc1 = __hadd2(hacc1, *(__half2*)&r.y);
        hacc2 = __hadd2(hacc2, *(__half2*)&r.z);
        hacc3 = __hadd2(hacc3, *(__half2*)&r.w);
    }

    float acc[8];
    {
        float2 a0 = __half22float2(hacc0);
        float2 a1 = __half22float2(hacc1);
        float2 a2 = __half22float2(hacc2);
        float2 a3 = __half22float2(hacc3);
        acc[0]=a0.x; acc[1]=a0.y; acc[2]=a1.x; acc[3]=a1.y;
        acc[4]=a2.x; acc[5]=a2.y; acc[6]=a3.x; acc[7]=a3.y;
    }

    float x0[8];
    loadRow8F_cs(x, row, sub, x0);          // streaming fp32 anchor

    const float cn = BETA_C * nv;
    const float sc = SCALE_OUT ? nv : fs;   // y_new = nv*h_new, or fs*h_new

    float r[8];
    #pragma unroll
    for (int k = 0; k < 8; k++)
        r[k] = fmaf(cn, acc[k], ALPHA_C * x0[k]) * sc;

    storeRow8(hdst, row, sub, r);
}

// ------------------------ step-1 kernel (fp32 src = x) ----------------------
// Mapping B coalesced gathers; per-edge w = g_norm[src] from the 1.2MB
// L2-resident table; folded self+anchor; stores y1 = nv*h1 (fp16).
__global__ void __launch_bounds__(256)
spmm_step1_kernel(const float* __restrict__ x, __half* __restrict__ hdst) {
    const int lane = threadIdx.x & 31;
    const int sub  = lane & 7;
    const int team = lane >> 3;
    const int warp = blockIdx.x * (blockDim.x >> 5) + (threadIdx.x >> 5);
    const unsigned row = warp * 4 + team;

    const int2 info = g_rowinfo[row];
    const int  st   = info.x;
    const int  len  = info.y;
    const float nv  = rsqrtf((float)(len + 1));

    float acc[8];
    #pragma unroll
    for (int k = 0; k < 8; k++) acc[k] = 0.f;

    const int n16 = (len < 16) ? len : 16;
    unsigned s0 = 0u, s1 = 0u;
    float    w0 = 0.f, w1 = 0.f;
    if (sub < n16)     { s0 = g_edge[st + sub];     w0 = g_norm[s0]; }
    if (sub + 8 < n16) { s1 = g_edge[st + sub + 8]; w1 = g_norm[s1]; }

    #pragma unroll
    for (int j = 0; j < 16; j++) {
        unsigned sx = __shfl_sync(0xFFFFFFFFu, (j < 8) ? s0 : s1, j & 7, 8);
        float    w  = __shfl_sync(0xFFFFFFFFu, (j < 8) ? w0 : w1, j & 7, 8);
        if (j < n16) {
            float v[8];
            loadRowB(x, sx, sub, v);
            #pragma unroll
            for (int k = 0; k < 8; k++) acc[k] = fmaf(w, v[k], acc[k]);
        }
    }

    for (int j = 16; j < len; j++) {
        unsigned sx = g_edge[st + j];
        float w = g_norm[sx];
        float v[8];
        loadRowB(x, sx, sub, v);
        #pragma unroll
        for (int k = 0; k < 8; k++) acc[k] = fmaf(w, v[k], acc[k]);
    }

    float sh[8];
    loadRowB(x, row, sub, sh);

    const float cn = BETA_C * nv;
    const float ca = BETA_C * nv * nv + ALPHA_C;    // folded self + anchor

    float r[8];
    #pragma unroll
    for (int k = 0; k < 8; k++)
        r[k] = fmaf(cn, acc[k], ca * sh[k]) * nv;   // store y1 = nv*h1

    storeRowB(hdst, row, sub, r);
}

// --------------------------------- launch ----------------------------------
extern "C" void kernel_launch(void* const* d_in, const int* in_sizes, int n_in,
                              void* d_out, int out_size) {
    const float* x    = (const float*)d_in[0];
    const int*   uidx = (const int*)  d_in[1];
    const int*   iidx = (const int*)  d_in[2];
    float*       out  = (float*)d_out;

    const int T = 256;

    void* p_cnt   = nullptr; cudaGetSymbolAddress(&p_cnt,   g_cnt);
    void* p_alloc = nullptr; cudaGetSymbolAddress(&p_alloc, g_alloc);
    void* p_hh    = nullptr; cudaGetSymbolAddress(&p_hh,    g_hh);
    __half* h0 = (__half*)p_hh;
    __half* h1 = h0 + (size_t)NN * DD;

    // ---- CSR build ----
    cudaMemsetAsync(p_cnt,   0, sizeof(int) * NN);
    cudaMemsetAsync(p_alloc, 0, sizeof(int));
    count_kernel<<<(NE + T - 1) / T, T>>>(uidx, iidx);
    alloc_kernel<<<(NN + T - 1) / T, T>>>();
    fill_kernel <<<(NE + T - 1) / T, T>>>(uidx, iidx);

    // ---- K = 4 diffusion steps (y = norm*h representation) ----
    const int rows_per_blk = (T / 32) * 4;            // 32 rows / block
    const int spmm_blocks  = (NN + rows_per_blk - 1) / rows_per_blk;

    spmm_step1_kernel<<<spmm_blocks, T>>>(x, h0);                       // y1
    spmm_kernel<__half, true ><<<spmm_blocks, T>>>(h0, h1, x, 1.0f);    // y2
    spmm_kernel<__half, true ><<<spmm_blocks, T>>>(h1, h0, x, 1.0f);    // y3
    spmm_kernel<float,  false><<<spmm_blocks, T>>>(h0, out, x, INV_GAMMA);
}

// round 16
// speedup vs baseline: 1.2358x; 1.0087x over previous
#include <cuda_runtime.h>
#include <cuda_fp16.h>
#include <cstdint>

// ---------------------------------------------------------------------------
// MGDCF diffusion: h_{t+1} = BETA * A_norm h_t + ALPHA * h0, K=4 steps.
// Round 15: uniform weightless pipeline. convert computes y0 = norm*x (fp16,
// into h0); then ALL FOUR steps are the generic spmm kernel:
//   h_new = beta*nv*(sum_j y_j + y_self) + alpha*x ,  store nv*h_new
// (final step stores fs*h_new to fp32 out). Edges are 4B (src only);
// hot loop = 1 shuffle + LDG.128 + 4x HADD2 per slot. Specialized fp32
// step-1 kernel deleted.
// ---------------------------------------------------------------------------

#define NUSERS 200000
#define NITEMS 100000
#define NN     300000              // total nodes (div by 4 -> exact tiling)
#define NE     1000000             // user-item pairs
#define DD     64                  // feature dim

static constexpr float ALPHA_C = 0.1f;
static constexpr float BETA_C  = 0.9f;
static constexpr double GAMMA_D =
    (0.9 * 0.9 * 0.9 * 0.9) + 0.1 * (1.0 + 0.9 + 0.81 + 0.729);   // = 1.0
static constexpr float INV_GAMMA = (float)(1.0 / GAMMA_D);

// ------------------------- device scratch (static) -------------------------
__device__ __half   g_hh[2][(size_t)NN * DD]; // ping-pong fp16 y buffers
__device__ int      g_cnt[NN];                // real in-degree (excl. self)
__device__ float    g_norm[NN];               // (deg incl. self)^-1/2
__device__ int2     g_rowinfo[NN];            // (segment start, in-degree)
__device__ int      g_cursor[NN];             // fill cursors
__device__ unsigned g_edge[2 * NE];           // src only, 8 MB
__device__ int      g_alloc;                  // global segment allocator

// ------------------------------ build kernels ------------------------------

__global__ void count_kernel(const int* __restrict__ uidx,
                             const int* __restrict__ iidx) {
    int e = blockIdx.x * blockDim.x + threadIdx.x;
    if (e >= NE) return;
    int u  = uidx[e];
    int it = iidx[e] + NUSERS;
    atomicAdd(&g_cnt[u], 1);
    atomicAdd(&g_cnt[it], 1);
}

// Block-aggregated segment allocation: warp scan -> smem warp totals ->
// width-8 scan -> ONE global atomic per block.
__global__ void alloc_kernel() {
    __shared__ int warp_pref[8];
    __shared__ int block_base;

    int v    = blockIdx.x * blockDim.x + threadIdx.x;
    int lane = threadIdx.x & 31;
    int wid  = threadIdx.x >> 5;

    int c = 0;
    if (v < NN) {
        c = g_cnt[v];
        g_norm[v] = rsqrtf((float)(c + 1));
    }
    int inc = c;
    #pragma unroll
    for (int o = 1; o < 32; o <<= 1) {
        int t = __shfl_up_sync(0xFFFFFFFFu, inc, o);
        if (lane >= o) inc += t;
    }
    if (lane == 31) warp_pref[wid] = inc;
    __syncthreads();

    if (threadIdx.x < 8) {
        int t = warp_pref[threadIdx.x];
        int s = t;
        #pragma unroll
        for (int o = 1; o < 8; o <<= 1) {
            int tt = __shfl_up_sync(0xFFu, s, o, 8);
            if (threadIdx.x >= o) s += tt;
        }
        warp_pref[threadIdx.x] = s - t;
        if (threadIdx.x == 7)
            block_base = atomicAdd(&g_alloc, s);
    }
    __syncthreads();

    if (v < NN) {
        int st = block_base + warp_pref[wid] + inc - c;
        g_rowinfo[v] = make_int2(st, c);
        g_cursor[v]  = st;
    }
}

// fill: 4B edge payload (src only).
__global__ void fill_kernel(const int* __restrict__ uidx,
                            const int* __restrict__ iidx) {
    int e = blockIdx.x * blockDim.x + threadIdx.x;
    if (e >= NE) return;
    int u  = uidx[e];
    int it = iidx[e] + NUSERS;
    int p0 = atomicAdd(&g_cursor[it], 1);
    g_edge[p0] = (unsigned)u;                // edge u -> it (dst = it)
    int p1 = atomicAdd(&g_cursor[u], 1);
    g_edge[p1] = (unsigned)it;               // edge it -> u (dst = u)
}

// convert: y0 = norm[row] * x, fp16, fully coalesced (16B in, 8B out / thread)
__global__ void __launch_bounds__(256)
convert_kernel(const float* __restrict__ x, __half* __restrict__ y0) {
    unsigned i = blockIdx.x * blockDim.x + threadIdx.x;  // one float4 per thread
    if (i >= (unsigned)(NN * (DD / 4))) return;
    unsigned row = i >> 4;                   // DD/4 = 16 float4s per row
    float nv = g_norm[row];
    float4 v = ((const float4*)x)[i];
    __half2 a = __floats2half2_rn(nv * v.x, nv * v.y);
    __half2 b = __floats2half2_rn(nv * v.z, nv * v.w);
    uint2 r;
    r.x = *(unsigned*)&a;
    r.y = *(unsigned*)&b;
    ((uint2*)y0)[i] = r;
}

// ----------------------- 8-wide row load/store helpers ----------------------
// Mapping A (fp16 rows): lane `sub` owns columns [sub*8, sub*8+8).

__device__ __forceinline__ void loadRow8F_cs(const float* __restrict__ h,
                                             unsigned row, int sub, float v[8]) {
    const float4* p = (const float4*)(h + (size_t)row * DD) + sub * 2;
    float4 a = __ldcs(p);
    float4 b = __ldcs(p + 1);
    v[0]=a.x; v[1]=a.y; v[2]=a.z; v[3]=a.w;
    v[4]=b.x; v[5]=b.y; v[6]=b.z; v[7]=b.w;
}
__device__ __forceinline__ void storeRow8(float* __restrict__ h,
                                          unsigned row, int sub, const float v[8]) {
    float4* p = (float4*)(h + (size_t)row * DD) + sub * 2;
    __stcs(p,     make_float4(v[0], v[1], v[2], v[3]));
    __stcs(p + 1, make_float4(v[4], v[5], v[6], v[7]));
}
__device__ __forceinline__ void storeRow8(__half* __restrict__ h,
                                          unsigned row, int sub, const float v[8]) {
    __half2 h0 = __floats2half2_rn(v[0], v[1]);
    __half2 h1 = __floats2half2_rn(v[2], v[3]);
    __half2 h2 = __floats2half2_rn(v[4], v[5]);
    __half2 h3 = __floats2half2_rn(v[6], v[7]);
    uint4 r;
    r.x = *(unsigned*)&h0;  r.y = *(unsigned*)&h1;
    r.z = *(unsigned*)&h2;  r.w = *(unsigned*)&h3;
    ((uint4*)(h + (size_t)row * DD))[sub] = r;
}

// --------------------------- SpMM kernel (fp16 y src) -----------------------
// Four rows per warp, 8 lanes/row, mapping A. Source is y = norm*h (fp16):
// hot loop is 1 shuffle + LDG.128 + 4x HADD2 per slot (no weight).
// h_new = cn*(sum_j y_j + y_self) + alpha*x ; store nv*h_new (mid steps)
// or fs*h_new (final fp32 out).
template <typename DstT, bool SCALE_OUT>
__global__ void __launch_bounds__(256, 6)
spmm_kernel(const __half* __restrict__ ysrc, DstT* __restrict__ hdst,
            const float* __restrict__ x, float fs) {
    const int lane = threadIdx.x & 31;
    const int sub  = lane & 7;
    const int team = lane >> 3;
    const int warp = blockIdx.x * (blockDim.x >> 5) + (threadIdx.x >> 5);
    const unsigned row = warp * 4 + team;   // exact tiling: never >= NN

    const int2 info = g_rowinfo[row];
    const int  st   = info.x;
    const int  len  = info.y;
    const float nv  = rsqrtf((float)(len + 1));

    __half2 hacc0 = __float2half2_rn(0.f);
    __half2 hacc1 = hacc0, hacc2 = hacc0, hacc3 = hacc0;

    if (row < NUSERS) {
        // ---- user rows: 8 unrolled slots ----
        const int n8 = (len < 8) ? len : 8;
        unsigned s0 = 0u;
        if (sub < n8) s0 = g_edge[st + sub];
        #pragma unroll
        for (int j = 0; j < 8; j++) {
            unsigned sx = __shfl_sync(0xFFFFFFFFu, s0, j, 8);
            if (j < n8) {
                uint4 r = ((const uint4*)(ysrc + (size_t)sx * DD))[sub];
                hacc0 = __hadd2(hacc0, *(__half2*)&r.x);
                hacc1 = __hadd2(hacc1, *(__half2*)&r.y);
                hacc2 = __hadd2(hacc2, *(__half2*)&r.z);
                hacc3 = __hadd2(hacc3, *(__half2*)&r.w);
            }
        }
        for (int j = 8; j < len; j++) {               // deg > 8 tail (~7%)
            unsigned sx = g_edge[st + j];
            uint4 r = ((const uint4*)(ysrc + (size_t)sx * DD))[sub];
            hacc0 = __hadd2(hacc0, *(__half2*)&r.x);
            hacc1 = __hadd2(hacc1, *(__half2*)&r.y);
            hacc2 = __hadd2(hacc2, *(__half2*)&r.z);
            hacc3 = __hadd2(hacc3, *(__half2*)&r.w);
        }
    } else {
        // ---- item rows: 16 unrolled slots ----
        const int n16 = (len < 16) ? len : 16;
        unsigned s0 = 0u, s1 = 0u;
        if (sub < n16)     s0 = g_edge[st + sub];
        if (sub + 8 < n16) s1 = g_edge[st + sub + 8];
        #pragma unroll
        for (int j = 0; j < 16; j++) {
            unsigned sx = __shfl_sync(0xFFFFFFFFu, (j < 8) ? s0 : s1, j & 7, 8);
            if (j < n16) {
                uint4 r = ((const uint4*)(ysrc + (size_t)sx * DD))[sub];
                hacc0 = __hadd2(hacc0, *(__half2*)&r.x);
                hacc1 = __hadd2(hacc1, *(__half2*)&r.y);
                hacc2 = __hadd2(hacc2, *(__half2*)&r.z);
                hacc3 = __hadd2(hacc3, *(__half2*)&r.w);
            }
        }
        for (int j = 16; j < len; j++) {              // deg > 16 tail (rare)
            unsigned sx = g_edge[st + j];
            uint4 r = ((const uint4*)(ysrc + (size_t)sx * DD))[sub];
            hacc0 = __hadd2(hacc0, *(__half2*)&r.x);
            hacc1 = __hadd2(hacc1, *(__half2*)&r.y);
            hacc2 = __hadd2(hacc2, *(__half2*)&r.z);
            hacc3 = __hadd2(hacc3, *(__half2*)&r.w);
        }
    }

    // y_self folds into the neighbor sum (same coefficient cn)
    {
        uint4 r = ((const uint4*)(ysrc + (size_t)row * DD))[sub];
        hacc0 = __hadd2(hacc0, *(__half2*)&r.x);
        hacc1 = __hadd2(hacc1, *(__half2*)&r.y);
        hacc2 = __hadd2(hacc2, *(__half2*)&r.z);
        hacc3 = __hadd2(hacc3, *(__half2*)&r.w);
    }

    float acc[8];
    {
        float2 a0 = __half22float2(hacc0);
        float2 a1 = __half22float2(hacc1);
        float2 a2 = __half22float2(hacc2);
        float2 a3 = __half22float2(hacc3);
        acc[0]=a0.x; acc[1]=a0.y; acc[2]=a1.x; acc[3]=a1.y;
        acc[4]=a2.x; acc[5]=a2.y; acc[6]=a3.x; acc[7]=a3.y;
    }

    float x0[8];
    loadRow8F_cs(x, row, sub, x0);          // streaming fp32 anchor

    const float cn = BETA_C * nv;
    const float sc = SCALE_OUT ? nv : fs;   // y_new = nv*h_new, or fs*h_new

    float r[8];
    #pragma unroll
    for (int k = 0; k < 8; k++)
        r[k] = fmaf(cn, acc[k], ALPHA_C * x0[k]) * sc;

    storeRow8(hdst, row, sub, r);
}

// --------------------------------- launch ----------------------------------
extern "C" void kernel_launch(void* const* d_in, const int* in_sizes, int n_in,
                              void* d_out, int out_size) {
    const float* x    = (const float*)d_in[0];
    const int*   uidx = (const int*)  d_in[1];
    const int*   iidx = (const int*)  d_in[2];
    float*       out  = (float*)d_out;

    const int T = 256;

    void* p_cnt   = nullptr; cudaGetSymbolAddress(&p_cnt,   g_cnt);
    void* p_alloc = nullptr; cudaGetSymbolAddress(&p_alloc, g_alloc);
    void* p_hh    = nullptr; cudaGetSymbolAddress(&p_hh,    g_hh);
    __half* h0 = (__half*)p_hh;
    __half* h1 = h0 + (size_t)NN * DD;

    // ---- CSR build + y0 convert ----
    cudaMemsetAsync(p_cnt,   0, sizeof(int) * NN);
    cudaMemsetAsync(p_alloc, 0, sizeof(int));
    count_kernel<<<(NE + T - 1) / T, T>>>(uidx, iidx);
    alloc_kernel<<<(NN + T - 1) / T, T>>>();
    convert_kernel<<<(NN * (DD / 4) + T - 1) / T, T>>>(x, h0);   // y0 = nv*x
    fill_kernel <<<(NE + T - 1) / T, T>>>(uidx, iidx);

    // ---- K = 4 uniform diffusion steps (y = norm*h representation) ----
    const int rows_per_blk = (T / 32) * 4;            // 32 rows / block
    const int spmm_blocks  = (NN + rows_per_blk - 1) / rows_per_blk;

    spmm_kernel<__half, true ><<<spmm_blocks, T>>>(h0, h1, x, 1.0f);    // y1
    spmm_kernel<__half, true ><<<spmm_blocks, T>>>(h1, h0, x, 1.0f);    // y2
    spmm_kernel<__half, true ><<<spmm_blocks, T>>>(h0, h1, x, 1.0f);    // y3
    spmm_kernel<float,  false><<<spmm_blocks, T>>>(h1, out, x, INV_GAMMA);
}

// round 17
// speedup vs baseline: 1.2403x; 1.0037x over previous
#include <cuda_runtime.h>
#include <cuda_fp16.h>
#include <cstdint>

// ---------------------------------------------------------------------------
// MGDCF diffusion: h_{t+1} = BETA * A_norm h_t + ALPHA * h0, K=4 steps.
// Round 16: R15 base + fp16 streamed anchor. convert writes BOTH
// y0 = norm*x (into h0) and xh = fp16(x) (static buffer). All four uniform
// spmm steps read the alpha-anchor from xh via __ldcs (evict-first), cutting
// 39 MB/step of fp32 anchor traffic without polluting the gather set.
// ---------------------------------------------------------------------------

#define NUSERS 200000
#define NITEMS 100000
#define NN     300000              // total nodes (div by 4 -> exact tiling)
#define NE     1000000             // user-item pairs
#define DD     64                  // feature dim

static constexpr float ALPHA_C = 0.1f;
static constexpr float BETA_C  = 0.9f;
static constexpr double GAMMA_D =
    (0.9 * 0.9 * 0.9 * 0.9) + 0.1 * (1.0 + 0.9 + 0.81 + 0.729);   // = 1.0
static constexpr float INV_GAMMA = (float)(1.0 / GAMMA_D);

// ------------------------- device scratch (static) -------------------------
__device__ __half   g_hh[2][(size_t)NN * DD]; // ping-pong fp16 y buffers
__device__ __half   g_xh[(size_t)NN * DD];    // fp16 copy of x (anchor), 38.4 MB
__device__ int      g_cnt[NN];                // real in-degree (excl. self)
__device__ float    g_norm[NN];               // (deg incl. self)^-1/2
__device__ int2     g_rowinfo[NN];            // (segment start, in-degree)
__device__ int      g_cursor[NN];             // fill cursors
__device__ unsigned g_edge[2 * NE];           // src only, 8 MB
__device__ int      g_alloc;                  // global segment allocator

// ------------------------------ build kernels ------------------------------

__global__ void count_kernel(const int* __restrict__ uidx,
                             const int* __restrict__ iidx) {
    int e = blockIdx.x * blockDim.x + threadIdx.x;
    if (e >= NE) return;
    int u  = uidx[e];
    int it = iidx[e] + NUSERS;
    atomicAdd(&g_cnt[u], 1);
    atomicAdd(&g_cnt[it], 1);
}

// Block-aggregated segment allocation: warp scan -> smem warp totals ->
// width-8 scan -> ONE global atomic per block.
__global__ void alloc_kernel() {
    __shared__ int warp_pref[8];
    __shared__ int block_base;

    int v    = blockIdx.x * blockDim.x + threadIdx.x;
    int lane = threadIdx.x & 31;
    int wid  = threadIdx.x >> 5;

    int c = 0;
    if (v < NN) {
        c = g_cnt[v];
        g_norm[v] = rsqrtf((float)(c + 1));
    }
    int inc = c;
    #pragma unroll
    for (int o = 1; o < 32; o <<= 1) {
        int t = __shfl_up_sync(0xFFFFFFFFu, inc, o);
        if (lane >= o) inc += t;
    }
    if (lane == 31) warp_pref[wid] = inc;
    __syncthreads();

    if (threadIdx.x < 8) {
        int t = warp_pref[threadIdx.x];
        int s = t;
        #pragma unroll
        for (int o = 1; o < 8; o <<= 1) {
            int tt = __shfl_up_sync(0xFFu, s, o, 8);
            if (threadIdx.x >= o) s += tt;
        }
        warp_pref[threadIdx.x] = s - t;
        if (threadIdx.x == 7)
            block_base = atomicAdd(&g_alloc, s);
    }
    __syncthreads();

    if (v < NN) {
        int st = block_base + warp_pref[wid] + inc - c;
        g_rowinfo[v] = make_int2(st, c);
        g_cursor[v]  = st;
    }
}

// fill: 4B edge payload (src only).
__global__ void fill_kernel(const int* __restrict__ uidx,
                            const int* __restrict__ iidx) {
    int e = blockIdx.x * blockDim.x + threadIdx.x;
    if (e >= NE) return;
    int u  = uidx[e];
    int it = iidx[e] + NUSERS;
    int p0 = atomicAdd(&g_cursor[it], 1);
    g_edge[p0] = (unsigned)u;                // edge u -> it (dst = it)
    int p1 = atomicAdd(&g_cursor[u], 1);
    g_edge[p1] = (unsigned)it;               // edge it -> u (dst = u)
}

// convert: writes y0 = norm[row]*x (into h0) AND xh = fp16(x).
__global__ void __launch_bounds__(256)
convert_kernel(const float* __restrict__ x, __half* __restrict__ y0) {
    unsigned i = blockIdx.x * blockDim.x + threadIdx.x;  // one float4 per thread
    if (i >= (unsigned)(NN * (DD / 4))) return;
    unsigned row = i >> 4;                   // DD/4 = 16 float4s per row
    float nv = g_norm[row];
    float4 v = ((const float4*)x)[i];
    // xh = fp16(x)
    {
        __half2 a = __floats2half2_rn(v.x, v.y);
        __half2 b = __floats2half2_rn(v.z, v.w);
        uint2 r;
        r.x = *(unsigned*)&a;
        r.y = *(unsigned*)&b;
        ((uint2*)g_xh)[i] = r;
    }
    // y0 = nv * x
    {
        __half2 a = __floats2half2_rn(nv * v.x, nv * v.y);
        __half2 b = __floats2half2_rn(nv * v.z, nv * v.w);
        uint2 r;
        r.x = *(unsigned*)&a;
        r.y = *(unsigned*)&b;
        ((uint2*)y0)[i] = r;
    }
}

// ----------------------- 8-wide row load/store helpers ----------------------
// Mapping A (fp16 rows): lane `sub` owns columns [sub*8, sub*8+8).

// fp16 anchor read, streaming (evict-first, no L2 pollution)
__device__ __forceinline__ void loadRow8H_cs(const __half* __restrict__ h,
                                             unsigned row, int sub, float v[8]) {
    uint4 r = __ldcs((const uint4*)(h + (size_t)row * DD) + sub);
    float2 f0 = __half22float2(*(__half2*)&r.x);
    float2 f1 = __half22float2(*(__half2*)&r.y);
    float2 f2 = __half22float2(*(__half2*)&r.z);
    float2 f3 = __half22float2(*(__half2*)&r.w);
    v[0]=f0.x; v[1]=f0.y; v[2]=f1.x; v[3]=f1.y;
    v[4]=f2.x; v[5]=f2.y; v[6]=f3.x; v[7]=f3.y;
}
__device__ __forceinline__ void storeRow8(float* __restrict__ h,
                                          unsigned row, int sub, const float v[8]) {
    float4* p = (float4*)(h + (size_t)row * DD) + sub * 2;
    __stcs(p,     make_float4(v[0], v[1], v[2], v[3]));
    __stcs(p + 1, make_float4(v[4], v[5], v[6], v[7]));
}
__device__ __forceinline__ void storeRow8(__half* __restrict__ h,
                                          unsigned row, int sub, const float v[8]) {
    __half2 h0 = __floats2half2_rn(v[0], v[1]);
    __half2 h1 = __floats2half2_rn(v[2], v[3]);
    __half2 h2 = __floats2half2_rn(v[4], v[5]);
    __half2 h3 = __floats2half2_rn(v[6], v[7]);
    uint4 r;
    r.x = *(unsigned*)&h0;  r.y = *(unsigned*)&h1;
    r.z = *(unsigned*)&h2;  r.w = *(unsigned*)&h3;
    ((uint4*)(h + (size_t)row * DD))[sub] = r;
}

// --------------------------- SpMM kernel (fp16 y src) -----------------------
// Four rows per warp, 8 lanes/row, mapping A. Source is y = norm*h (fp16):
// hot loop is 1 shuffle + LDG.128 + 4x HADD2 per slot (no weight).
// h_new = cn*(sum_j y_j + y_self) + alpha*xh ; store nv*h_new (mid steps)
// or fs*h_new (final fp32 out).
template <typename DstT, bool SCALE_OUT>
__global__ void __launch_bounds__(256, 6)
spmm_kernel(const __half* __restrict__ ysrc, DstT* __restrict__ hdst, float fs) {
    const int lane = threadIdx.x & 31;
    const int sub  = lane & 7;
    const int team = lane >> 3;
    const int warp = blockIdx.x * (blockDim.x >> 5) + (threadIdx.x >> 5);
    const unsigned row = warp * 4 + team;   // exact tiling: never >= NN

    const int2 info = g_rowinfo[row];
    const int  st   = info.x;
    const int  len  = info.y;
    const float nv  = rsqrtf((float)(len + 1));

    __half2 hacc0 = __float2half2_rn(0.f);
    __half2 hacc1 = hacc0, hacc2 = hacc0, hacc3 = hacc0;

    if (row < NUSERS) {
        // ---- user rows: 8 unrolled slots ----
        const int n8 = (len < 8) ? len : 8;
        unsigned s0 = 0u;
        if (sub < n8) s0 = g_edge[st + sub];
        #pragma unroll
        for (int j = 0; j < 8; j++) {
            unsigned sx = __shfl_sync(0xFFFFFFFFu, s0, j, 8);
            if (j < n8) {
                uint4 r = ((const uint4*)(ysrc + (size_t)sx * DD))[sub];
                hacc0 = __hadd2(hacc0, *(__half2*)&r.x);
                hacc1 = __hadd2(hacc1, *(__half2*)&r.y);
                hacc2 = __hadd2(hacc2, *(__half2*)&r.z);
                hacc3 = __hadd2(hacc3, *(__half2*)&r.w);
            }
        }
        for (int j = 8; j < len; j++) {               // deg > 8 tail (~7%)
            unsigned sx = g_edge[st + j];
            uint4 r = ((const uint4*)(ysrc + (size_t)sx * DD))[sub];
            hacc0 = __hadd2(hacc0, *(__half2*)&r.x);
            hacc1 = __hadd2(hacc1, *(__half2*)&r.y);
            hacc2 = __hadd2(hacc2, *(__half2*)&r.z);
            hacc3 = __hadd2(hacc3, *(__half2*)&r.w);
        }
    } else {
        // ---- item rows: 16 unrolled slots ----
        const int n16 = (len < 16) ? len : 16;
        unsigned s0 = 0u, s1 = 0u;
        if (sub < n16)     s0 = g_edge[st + sub];
        if (sub + 8 < n16) s1 = g_edge[st + sub + 8];
        #pragma unroll
        for (int j = 0; j < 16; j++) {
            unsigned sx = __shfl_sync(0xFFFFFFFFu, (j < 8) ? s0 : s1, j & 7, 8);
            if (j < n16) {
                uint4 r = ((const uint4*)(ysrc + (size_t)sx * DD))[sub];
                hacc0 = __hadd2(hacc0, *(__half2*)&r.x);
                hacc1 = __hadd2(hacc1, *(__half2*)&r.y);
                hacc2 = __hadd2(hacc2, *(__half2*)&r.z);
                hacc3 = __hadd2(hacc3, *(__half2*)&r.w);
            }
        }
        for (int j = 16; j < len; j++) {              // deg > 16 tail (rare)
            unsigned sx = g_edge[st + j];
            uint4 r = ((const uint4*)(ysrc + (size_t)sx * DD))[sub];
            hacc0 = __hadd2(hacc0, *(__half2*)&r.x);
            hacc1 = __hadd2(hacc1, *(__half2*)&r.y);
            hacc2 = __hadd2(hacc2, *(__half2*)&r.z);
            hacc3 = __hadd2(hacc3, *(__half2*)&r.w);
        }
    }

    // y_self folds into the neighbor sum (same coefficient cn)
    {
        uint4 r = ((const uint4*)(ysrc + (size_t)row * DD))[sub];
        hacc0 = __hadd2(hacc0, *(__half2*)&r.x);
        hacc1 = __hadd2(hacc1, *(__half2*)&r.y);
        hacc2 = __hadd2(hacc2, *(__half2*)&r.z);
        hacc3 = __hadd2(hacc3, *(__half2*)&r.w);
    }

    float acc[8];
    {
        float2 a0 = __half22float2(hacc0);
        float2 a1 = __half22float2(hacc1);
        float2 a2 = __half22float2(hacc2);
        float2 a3 = __half22float2(hacc3);
        acc[0]=a0.x; acc[1]=a0.y; acc[2]=a1.x; acc[3]=a1.y;
        acc[4]=a2.x; acc[5]=a2.y; acc[6]=a3.x; acc[7]=a3.y;
    }

    float x0[8];
    loadRow8H_cs(g_xh, row, sub, x0);       // streaming fp16 anchor

    const float cn = BETA_C * nv;
    const float sc = SCALE_OUT ? nv : fs;   // y_new = nv*h_new, or fs*h_new

    float r[8];
    #pragma unroll
    for (int k = 0; k < 8; k++)
        r[k] = fmaf(cn, acc[k], ALPHA_C * x0[k]) * sc;

    storeRow8(hdst, row, sub, r);
}

// --------------------------------- launch ----------------------------------
extern "C" void kernel_launch(void* const* d_in, const int* in_sizes, int n_in,
                              void* d_out, int out_size) {
    const float* x    = (const float*)d_in[0];
    const int*   uidx = (const int*)  d_in[1];
    const int*   iidx = (const int*)  d_in[2];
    float*       out  = (float*)d_out;

    const int T = 256;

    void* p_cnt   = nullptr; cudaGetSymbolAddress(&p_cnt,   g_cnt);
    void* p_alloc = nullptr; cudaGetSymbolAddress(&p_alloc, g_alloc);
    void* p_hh    = nullptr; cudaGetSymbolAddress(&p_hh,    g_hh);
    __half* h0 = (__half*)p_hh;
    __half* h1 = h0 + (size_t)NN * DD;

    // ---- CSR build + converts ----
    cudaMemsetAsync(p_cnt,   0, sizeof(int) * NN);
    cudaMemsetAsync(p_alloc, 0, sizeof(int));
    count_kernel<<<(NE + T - 1) / T, T>>>(uidx, iidx);
    alloc_kernel<<<(NN + T - 1) / T, T>>>();
    convert_kernel<<<(NN * (DD / 4) + T - 1) / T, T>>>(x, h0);  // y0 + xh
    fill_kernel <<<(NE + T - 1) / T, T>>>(uidx, iidx);

    // ---- K = 4 uniform diffusion steps (y = norm*h representation) ----
    const int rows_per_blk = (T / 32) * 4;            // 32 rows / block
    const int spmm_blocks  = (NN + rows_per_blk - 1) / rows_per_blk;

    spmm_kernel<__half, true ><<<spmm_blocks, T>>>(h0, h1, 1.0f);    // y1
    spmm_kernel<__half, true ><<<spmm_blocks, T>>>(h1, h0, 1.0f);    // y2
    spmm_kernel<__half, true ><<<spmm_blocks, T>>>(h0, h1, 1.0f);    // y3
    spmm_kernel<float,  false><<<spmm_blocks, T>>>(h1, out, INV_GAMMA);
}